// round 16
// baseline (speedup 1.0000x reference)
#include <cuda_runtime.h>
#include <cuda_bf16.h>
#include <cuda_fp16.h>
#include <math.h>
#include <float.h>
#include <stdint.h>

// Problem constants
#define Bv 64
#define Tv 512
#define Dv 256
#define Mv 1024
#define NROWS (Bv*Tv)          // 32768
#define BTD ((size_t)NROWS*Dv) // 8388608
#define NCHUNK 4               // phase2 T-split
#define NTILE 8                // 1024/128 col tiles
#define ESCALE 16777216.0f     // 2^24
#define DELTA_D 2.0e-3f        // dist-space safety window (bf16 GEMM error), proven in R11
#define FP16_SLACK 6.0e-4f     // > 2^-11 fp16 round-to-nearest bound
#define CAND_CAP 63            // R13-15 failures were cap-15 overflow (mean count ~5-16)

// ---------------- static device scratch ----------------
__device__ __align__(16) __half g_e16[2][(size_t)NROWS*Mv];   // 128 MB scaled exp
__device__ float g_psum[2][NROWS][NTILE];                      // per-tile row sums
__device__ float g_tmin[2][NROWS][NTILE];                      // per-tile row min d
__device__ float g_inv2[2][NROWS];                             // 1/(sum*Tv*2^24)
__device__ float g_thr[2][NROWS];                              // fp16-e candidate threshold
__device__ float g_norm_a[NROWS];
__device__ float g_norm_e[NROWS];
__device__ float g_norm_emb[Mv];
__device__ int   g_idx_a[NROWS];
__device__ int   g_idx_e[NROWS];
__device__ int   g_cand[2][NROWS][64];     // [0]=cnt, [1..63]=candidate idx
__device__ float g_php[2][Bv][NCHUNK][Mv];
__device__ float g_ph[2][Bv][Mv];
__device__ float g_lph[2][Bv][Mv];
__device__ int   g_cnt[2][Bv][Mv];
__device__ int   g_mode[2][Bv];
__device__ float g_scode[Bv][Bv];
__device__ float g_lpart[NROWS*4];
__device__ __align__(16) __nv_bfloat16 g_hiA[2][BTD];
__device__ __align__(16) __nv_bfloat16 g_hiB[Mv*Dv];

// ==================== PTX helpers (sm_80-compatible only) ====================
__device__ __forceinline__ uint32_t smem_u32(const void* p) {
    uint32_t a;
    asm("{ .reg .u64 t; cvta.to.shared.u64 t, %1; cvt.u32.u64 %0, t; }" : "=r"(a) : "l"(p));
    return a;
}
__device__ __forceinline__ void cp16(uint32_t s, const void* g) {
    asm volatile("cp.async.cg.shared.global [%0], [%1], 16;" :: "r"(s), "l"(g));
}
__device__ __forceinline__ void cp_commit() { asm volatile("cp.async.commit_group;" ::: "memory"); }
template<int N>
__device__ __forceinline__ void cp_wait() { asm volatile("cp.async.wait_group %0;" :: "n"(N) : "memory"); }

__device__ __forceinline__ void ldsm4(uint32_t* r, uint32_t addr) {
    asm volatile("ldmatrix.sync.aligned.m8n8.x4.shared.b16 {%0,%1,%2,%3}, [%4];"
        : "=r"(r[0]), "=r"(r[1]), "=r"(r[2]), "=r"(r[3]) : "r"(addr));
}
__device__ __forceinline__ void mma_bf16(float* c, const uint32_t* a, const uint32_t* b) {
    asm volatile("mma.sync.aligned.m16n8k16.row.col.f32.bf16.bf16.f32 "
        "{%0,%1,%2,%3}, {%4,%5,%6,%7}, {%8,%9}, {%0,%1,%2,%3};"
        : "+f"(c[0]), "+f"(c[1]), "+f"(c[2]), "+f"(c[3])
        : "r"(a[0]), "r"(a[1]), "r"(a[2]), "r"(a[3]), "r"(b[0]), "r"(b[1]));
}
__device__ __forceinline__ uint32_t sw128(uint32_t o) { return o ^ ((o >> 3) & 0x70); }

// ---------------- fused convert(fp32->bf16) + row norms (warp-per-row, MLP=2) ----------------
__global__ __launch_bounds__(256)
void conv_norm_kernel(const float* __restrict__ src,
                      __nv_bfloat16* __restrict__ dstB,
                      float* __restrict__ dstN) {
    const int wid = threadIdx.x >> 5, lane = threadIdx.x & 31;
    const int row = blockIdx.x * 8 + wid;
    const float4* s4 = (const float4*)(src + (size_t)row * Dv);
    float4 v0 = s4[lane];
    float4 v1 = s4[lane + 32];
    union { __nv_bfloat16 b[4]; uint2 u; } H0, H1;
    H0.b[0] = __float2bfloat16(v0.x); H0.b[1] = __float2bfloat16(v0.y);
    H0.b[2] = __float2bfloat16(v0.z); H0.b[3] = __float2bfloat16(v0.w);
    H1.b[0] = __float2bfloat16(v1.x); H1.b[1] = __float2bfloat16(v1.y);
    H1.b[2] = __float2bfloat16(v1.z); H1.b[3] = __float2bfloat16(v1.w);
    uint2* d4 = (uint2*)(dstB + (size_t)row * Dv);
    d4[lane] = H0.u;
    d4[lane + 32] = H1.u;
    float ss = v0.x*v0.x + v0.y*v0.y + v0.z*v0.z + v0.w*v0.w
             + v1.x*v1.x + v1.y*v1.y + v1.z*v1.z + v1.w*v1.w;
    #pragma unroll
    for (int off = 16; off; off >>= 1) ss += __shfl_xor_sync(0xffffffffu, ss, off);
    if (lane == 0) dstN[row] = ss;
}

// ---------------- HMMA bf16 GEMM -> fp16 exp + per-tile (sum, min) ----------------
#define TILE_B   16384
#define STAGE_B  (2*TILE_B)
#define NBUF     3
#define GEMM_SMEM (NBUF*STAGE_B)       // 96 KB

__device__ __forceinline__ void load_stage(uint32_t stBase, int rowBase, int colBase, int s,
                                           const __nv_bfloat16* __restrict__ Ahi,
                                           int tid) {
    #pragma unroll
    for (int j = 0; j < 8; ++j) {
        int id = j * 256 + tid;
        int t = id >> 10;
        int local = id & 1023;
        int row = local >> 3;
        int c = local & 7;
        const __nv_bfloat16* src = t ? g_hiB : Ahi;
        int grow = (t ? colBase : rowBase) + row;
        uint32_t so = stBase + t * TILE_B + sw128((uint32_t)(row * 128 + c * 16));
        cp16(so, src + (size_t)grow * Dv + s * 64 + c * 8);
    }
}

__global__ __launch_bounds__(256, 2)
void gemm_tc_kernel() {
    extern __shared__ char sm[];
    const uint32_t smem = smem_u32(sm);
    const int tid  = threadIdx.x;
    const int wid  = tid >> 5;
    const int lane = tid & 31;
    const int mod  = blockIdx.z;
    const int tileX = blockIdx.x;
    const int rowBase = blockIdx.y * 128;
    const int colBase = tileX * 128;
    const __nv_bfloat16* Ahi = g_hiA[mod];

    const int mb = (wid >> 2) * 64;
    const int nb = (wid & 3) * 32;

    const uint32_t aRow = (uint32_t)(mb + (lane & 15));
    const uint32_t aK16 = (uint32_t)((lane >> 4) * 16);
    const uint32_t bRow = (uint32_t)(nb + ((lane >> 4) << 3) + (lane & 7));
    const uint32_t bK16 = (uint32_t)(((lane >> 3) & 1) * 16);

    float acc[4][4][4];
    #pragma unroll
    for (int i = 0; i < 4; ++i)
        #pragma unroll
        for (int j = 0; j < 4; ++j)
            #pragma unroll
            for (int k = 0; k < 4; ++k) acc[i][j][k] = 0.f;

    load_stage(smem + 0 * STAGE_B, rowBase, colBase, 0, Ahi, tid); cp_commit();
    load_stage(smem + 1 * STAGE_B, rowBase, colBase, 1, Ahi, tid); cp_commit();
    load_stage(smem + 2 * STAGE_B, rowBase, colBase, 2, Ahi, tid); cp_commit();

    #pragma unroll
    for (int s = 0; s < 4; ++s) {
        if (s == 0) cp_wait<2>();
        else if (s == 1) cp_wait<2>();
        else if (s == 2) cp_wait<1>();
        else cp_wait<0>();
        __syncthreads();
        const uint32_t stBase = smem + (s % NBUF) * STAGE_B;
        const uint32_t aHiB = stBase;
        const uint32_t bHiB = stBase + TILE_B;

        #pragma unroll
        for (int kk = 0; kk < 4; ++kk) {
            const uint32_t kb = (uint32_t)(kk * 32);
            uint32_t ahi[4][4], bhi[2][4];
            #pragma unroll
            for (int mt = 0; mt < 4; ++mt) {
                uint32_t off = sw128((aRow + mt * 16) * 128 + kb + aK16);
                ldsm4(ahi[mt], aHiB + off);
            }
            #pragma unroll
            for (int p = 0; p < 2; ++p) {
                uint32_t off = sw128((bRow + p * 16) * 128 + kb + bK16);
                ldsm4(bhi[p], bHiB + off);
            }
            #pragma unroll
            for (int mt = 0; mt < 4; ++mt)
                #pragma unroll
                for (int nt = 0; nt < 4; ++nt)
                    mma_bf16(acc[mt][nt], ahi[mt], &bhi[nt >> 1][(nt & 1) * 2]);
        }
        if (s == 0) {
            __syncthreads();
            load_stage(smem + 0 * STAGE_B, rowBase, colBase, 3, Ahi, tid);
            cp_commit();
        }
    }
    __syncthreads();   // mainloop smem dead; overlay epilogue arrays

    float* ssum  = (float*)sm;                 // [128][4]
    float* sminv = ssum + 512;                 // [128][4]

    const float* rnArr = mod ? g_norm_e : g_norm_a;
    const int q = lane >> 2;
    const int cpair = (lane & 3) * 2;
    const int nwsub = wid & 3;

    // single pass: d, e (fp16*2^24 store), per-row partial sum/min
    #pragma unroll
    for (int mt = 0; mt < 4; ++mt) {
        #pragma unroll
        for (int half = 0; half < 2; ++half) {
            const int rloc = mb + mt * 16 + q + half * 8;
            const int grow = rowBase + rloc;
            const float rn = __ldg(&rnArr[grow]);
            float lsum = 0.f, lmin = FLT_MAX;
            #pragma unroll
            for (int nt = 0; nt < 4; ++nt) {
                const int col = colBase + nb + nt * 8 + cpair;
                const float2 ne = *(const float2*)&g_norm_emb[col];
                float d0 = rn + ne.x - 2.0f * acc[mt][nt][half * 2 + 0];
                float d1 = rn + ne.y - 2.0f * acc[mt][nt][half * 2 + 1];
                float e0 = __expf(-sqrtf(fmaxf(d0, 0.f)));
                float e1 = __expf(-sqrtf(fmaxf(d1, 0.f)));
                __half2 h = __floats2half2_rn(e0 * ESCALE, e1 * ESCALE);
                *(__half2*)(&g_e16[mod][(size_t)grow * Mv + col]) = h;
                lsum += e0 + e1;
                lmin = fminf(lmin, fminf(d0, d1));
            }
            #pragma unroll
            for (int o = 1; o <= 2; o <<= 1) {
                lsum += __shfl_xor_sync(0xffffffffu, lsum, o);
                lmin = fminf(lmin, __shfl_xor_sync(0xffffffffu, lmin, o));
            }
            if ((lane & 3) == 0) {
                ssum[rloc * 4 + nwsub] = lsum;
                sminv[rloc * 4 + nwsub] = lmin;
            }
        }
    }
    __syncthreads();
    if (tid < 128) {
        float s = 0.f, mn = FLT_MAX;
        #pragma unroll
        for (int c = 0; c < 4; ++c) {
            s += ssum[tid * 4 + c];
            mn = fminf(mn, sminv[tid * 4 + c]);
        }
        g_psum[mod][rowBase + tid][tileX] = s;
        g_tmin[mod][rowBase + tid][tileX] = mn;
    }
}

// ---------------- merge: row sums -> inv, mins -> fp16-e threshold ----------------
__global__ __launch_bounds__(256)
void merge_kernel() {
    const int row = blockIdx.x * 256 + threadIdx.x;
    const int mod = blockIdx.y;
    float s = 0.f, gmin = FLT_MAX;
    #pragma unroll
    for (int t = 0; t < NTILE; ++t) {
        s += g_psum[mod][row][t];
        gmin = fminf(gmin, g_tmin[mod][row][t]);
    }
    g_inv2[mod][row] = 1.0f / (s * ESCALE * (float)Tv);
    // true argmin's fp16-stored e guaranteed >= thr:
    // its bf16-dist <= gmin+DELTA_D; fp16 rounding < FP16_SLACK
    float thr = __expf(-sqrtf(fmaxf(gmin + DELTA_D, 0.f))) * (1.0f - FP16_SLACK) * ESCALE;
    g_thr[mod][row] = thr;
}

// ---------------- phase2: ph accumulation + threshold candidates from fp16 e ----------------
__global__ __launch_bounds__(256, 4)
void phase2_kernel() {
    const int b     = blockIdx.x;
    const int chunk = blockIdx.y;
    const int mod   = blockIdx.z;

    __shared__ float ph[8][Mv];   // per-warp private accumulators (32 KB)
    __shared__ int scand[8][CAND_CAP];
    __shared__ int scnt[8];

    const int tid = threadIdx.x;
    const int w = tid >> 5, lane = tid & 31;

    for (int m = lane; m < Mv; m += 32) ph[w][m] = 0.f;
    __syncthreads();

    const int t0 = chunk * (Tv / NCHUNK);
    const int t1 = t0 + (Tv / NCHUNK);
    for (int t = t0 + w; t < t1; t += 8) {
        const int row = b * Tv + t;
        const uint2* erow = (const uint2*)(&g_e16[mod][(size_t)row * Mv]);
        const float inv = g_inv2[mod][row];
        const float thr = g_thr[mod][row];
        if (lane == 0) scnt[w] = 0;
        __syncwarp();
        uint32_t lmask = 0;
        #pragma unroll
        for (int jj = 0; jj < 8; ++jj) {
            uint2 ev = erow[jj * 32 + lane];
            float2 f0 = __half22float2(*(__half2*)&ev.x);
            float2 f1 = __half22float2(*(__half2*)&ev.y);
            float4* p = (float4*)&ph[w][jj * 128 + lane * 4];
            float4 v = *p;
            v.x = fmaf(f0.x, inv, v.x);
            v.y = fmaf(f0.y, inv, v.y);
            v.z = fmaf(f1.x, inv, v.z);
            v.w = fmaf(f1.y, inv, v.w);
            *p = v;
            if (f0.x >= thr) lmask |= 1u << (jj*4+0);
            if (f0.y >= thr) lmask |= 1u << (jj*4+1);
            if (f1.x >= thr) lmask |= 1u << (jj*4+2);
            if (f1.y >= thr) lmask |= 1u << (jj*4+3);
        }
        while (lmask) {
            int bp = __ffs(lmask) - 1;
            lmask &= lmask - 1;
            int idx = (bp >> 2) * 128 + lane * 4 + (bp & 3);
            int pos = atomicAdd(&scnt[w], 1);
            if (pos < CAND_CAP) scand[w][pos] = idx;
        }
        __syncwarp();
        if (lane == 0) {
            int c = scnt[w]; if (c > CAND_CAP) c = CAND_CAP;
            int* dst = g_cand[mod][row];
            dst[0] = c;
            for (int k = 0; k < c; ++k) dst[k + 1] = scand[w][k];
        }
        __syncwarp();
    }
    __syncthreads();

    for (int m = tid; m < Mv; m += 256) {
        float v = 0.f;
        #pragma unroll
        for (int ww = 0; ww < 8; ++ww) v += ph[ww][m];
        g_php[mod][b][chunk][m] = v;
    }
}

// ---------------- ph finalize: chunk reduce + log (invT folded into inv2) ----------------
__global__ void ph_finalize_kernel() {
    const int b = blockIdx.x, mod = blockIdx.y;
    for (int m = threadIdx.x; m < Mv; m += 256) {
        float v = (g_php[mod][b][0][m] + g_php[mod][b][1][m])
                + (g_php[mod][b][2][m] + g_php[mod][b][3][m]);
        g_ph[mod][b][m]  = v;
        g_lph[mod][b][m] = logf(v + 1e-10f);
    }
}

// ---------------- refine: reference-rounding argmin over window candidates ----------------
__device__ __forceinline__ void dot2_acc(float a, float b, float& s, float& c) {
    float p  = a * b;
    float e1 = fmaf(a, b, -p);
    float t  = s + p;
    float z  = t - s;
    float e2 = (s - (t - z)) + (p - z);
    s = t;
    c += e1 + e2;
}

__global__ __launch_bounds__(256)
void refine_kernel(const float* __restrict__ audio,
                   const float* __restrict__ eeg,
                   const float* __restrict__ emb) {
    const int w = threadIdx.x >> 5, lane = threadIdx.x & 31;
    const int row = blockIdx.x * 8 + w;
    const int mod = blockIdx.y;
    const int* cd = g_cand[mod][row];
    int cnt = __ldg(&cd[0]);
    if (cnt <= 1) {
        if (lane == 0) (mod ? g_idx_e : g_idx_a)[row] = __ldg(&cd[1]);
        return;
    }
    if (cnt > CAND_CAP) cnt = CAND_CAP;

    const float* x = (mod ? eeg : audio) + (size_t)row * Dv;
    float xr[8];
    *(float4*)&xr[0] = *(const float4*)(x + lane * 8);
    *(float4*)&xr[4] = *(const float4*)(x + lane * 8 + 4);
    const float rn = (mod ? g_norm_e : g_norm_a)[row];

    float bestF = FLT_MAX; int bestI = 0x7fffffff;
    for (int k = 0; k < cnt; ++k) {
        int ci = __ldg(&cd[k + 1]);
        const float* e = emb + (size_t)ci * Dv + lane * 8;
        float4 a = *(const float4*)e;
        float4 bb = *(const float4*)(e + 4);
        float s = 0.f, comp = 0.f;
        dot2_acc(xr[0], a.x, s, comp);  dot2_acc(xr[1], a.y, s, comp);
        dot2_acc(xr[2], a.z, s, comp);  dot2_acc(xr[3], a.w, s, comp);
        dot2_acc(xr[4], bb.x, s, comp); dot2_acc(xr[5], bb.y, s, comp);
        dot2_acc(xr[6], bb.z, s, comp); dot2_acc(xr[7], bb.w, s, comp);
        float d = s + comp;
        #pragma unroll
        for (int off = 16; off; off >>= 1) d += __shfl_xor_sync(0xffffffffu, d, off);
        float tt = rn + g_norm_emb[ci];   // fp32 rounding (reference grid)
        float f  = tt - 2.0f * d;         // fp32 rounding
        if (f < bestF || (f == bestF && ci < bestI)) { bestF = f; bestI = ci; }
    }
    if (lane == 0) (mod ? g_idx_e : g_idx_a)[row] = bestI;
}

// ---------------- counts + mode per (b, mod) ----------------
__global__ __launch_bounds__(256)
void counts_kernel() {
    const int b = blockIdx.x;
    const int mod = blockIdx.y;
    const int tid = threadIdx.x;
    const int* idxArr = mod ? g_idx_e : g_idx_a;
    __shared__ int cnt[Mv];
    __shared__ int rbc[256], rbi[256];
    for (int m = tid; m < Mv; m += 256) cnt[m] = 0;
    __syncthreads();
    for (int t = tid; t < Tv; t += 256) atomicAdd(&cnt[idxArr[b * Tv + t]], 1);
    __syncthreads();
    for (int m = tid; m < Mv; m += 256) g_cnt[mod][b][m] = cnt[m];
    int bi = Mv, bc = -1;
    for (int m = tid; m < Mv; m += 256) {
        int cc = cnt[m];
        if (cc > bc) { bc = cc; bi = m; }
    }
    rbc[tid] = bc; rbi[tid] = bi;
    __syncthreads();
    for (int st = 128; st; st >>= 1) {
        if (tid < st) {
            if (rbc[tid + st] > rbc[tid] ||
                (rbc[tid + st] == rbc[tid] && rbi[tid + st] < rbi[tid])) {
                rbc[tid] = rbc[tid + st]; rbi[tid] = rbi[tid + st];
            }
        }
        __syncthreads();
    }
    if (tid == 0) g_mode[mod][b] = rbi[0];
}

// ---------------- Scode [64,64] ----------------
__global__ void scode_kernel() {
    __shared__ float ap[Mv], ep[Mv], partial[256];
    const int i = blockIdx.x, tid = threadIdx.x;
    for (int m = tid; m < Mv; m += 256) { ap[m] = g_ph[0][i][m]; ep[m] = g_ph[1][i][m]; }
    __syncthreads();
    const int j = tid & 63, part = tid >> 6;
    float sum = 0.f;
    const int k0 = part * 256;
    for (int k = k0; k < k0 + 256; ++k)
        sum += ap[k] * g_lph[1][j][k] + ep[k] * g_lph[0][j][k];
    partial[tid] = sum;
    __syncthreads();
    if (tid < 64)
        g_scode[i][tid] = partial[tid] + partial[tid + 64] + partial[tid + 128] + partial[tid + 192];
}

// ---------------- gather quantized outputs + MSE partials (vectorized) ----------------
__global__ __launch_bounds__(64)
void output_loss_kernel(const float* __restrict__ audio,
                        const float* __restrict__ eeg,
                        const float* __restrict__ emb,
                        float* __restrict__ out) {
    const int n = blockIdx.x;
    const int tid = threadIdx.x;
    const int ia = g_idx_a[n], ie = g_idx_e[n];
    const size_t off4 = (size_t)n * (Dv / 4) + tid;
    float4 av = ((const float4*)audio)[off4];
    float4 ev = ((const float4*)eeg)[off4];
    float4 qa = ((const float4*)(emb + (size_t)ia * Dv))[tid];
    float4 qe = ((const float4*)(emb + (size_t)ie * Dv))[tid];
    ((float4*)out)[off4]             = qa;
    ((float4*)out)[BTD / 4 + off4]   = qe;
    float daa = (av.x-qa.x)*(av.x-qa.x) + (av.y-qa.y)*(av.y-qa.y)
              + (av.z-qa.z)*(av.z-qa.z) + (av.w-qa.w)*(av.w-qa.w);
    float dae = (av.x-qe.x)*(av.x-qe.x) + (av.y-qe.y)*(av.y-qe.y)
              + (av.z-qe.z)*(av.z-qe.z) + (av.w-qe.w)*(av.w-qe.w);
    float dee = (ev.x-qe.x)*(ev.x-qe.x) + (ev.y-qe.y)*(ev.y-qe.y)
              + (ev.z-qe.z)*(ev.z-qe.z) + (ev.w-qe.w)*(ev.w-qe.w);
    float dea = (ev.x-qa.x)*(ev.x-qa.x) + (ev.y-qa.y)*(ev.y-qa.y)
              + (ev.z-qa.z)*(ev.z-qa.z) + (ev.w-qa.w)*(ev.w-qa.w);
    #pragma unroll
    for (int o = 16; o; o >>= 1) {
        daa += __shfl_xor_sync(0xffffffffu, daa, o);
        dae += __shfl_xor_sync(0xffffffffu, dae, o);
        dee += __shfl_xor_sync(0xffffffffu, dee, o);
        dea += __shfl_xor_sync(0xffffffffu, dea, o);
    }
    __shared__ float sred[4][2];
    const int w = tid >> 5, lane = tid & 31;
    if (lane == 0) { sred[0][w] = daa; sred[1][w] = dae; sred[2][w] = dee; sred[3][w] = dea; }
    __syncthreads();
    if (tid < 4) g_lpart[(size_t)n * 4 + tid] = sred[tid][0] + sred[tid][1];
}

// ---------------- scalars (also reduces MSE partials) ----------------
__device__ __forceinline__ float block_sum_1024(float v, float* red, int tid) {
    red[tid] = v; __syncthreads();
    for (int s = 512; s; s >>= 1) { if (tid < s) red[tid] += red[tid + s]; __syncthreads(); }
    float r = red[0]; __syncthreads(); return r;
}
__device__ __forceinline__ float block_min_1024(float v, float* red, int tid) {
    red[tid] = v; __syncthreads();
    for (int s = 512; s; s >>= 1) { if (tid < s) red[tid] = fminf(red[tid], red[tid + s]); __syncthreads(); }
    float r = red[0]; __syncthreads(); return r;
}

__global__ void final_kernel(float* __restrict__ out) {
    __shared__ float red[1024];
    __shared__ float sums4[4];
    const int tid = threadIdx.x;

    {
        const int c = tid & 3;
        float v = 0.f;
        for (int i = (tid >> 2); i < NROWS; i += 256) v += g_lpart[(size_t)i * 4 + c];
        red[tid] = v; __syncthreads();
        for (int s = 512; s >= 4; s >>= 1) {
            if (tid < s) red[tid] += red[tid + s];
            __syncthreads();
        }
        if (tid < 4) sums4[tid] = red[tid];
        __syncthreads();
    }

    int ca = 0, ce = 0;
    for (int b = 0; b < Bv; ++b) { ca += g_cnt[0][b][tid]; ce += g_cnt[1][b][tid]; }
    float avga = (float)ca * (1.0f / (float)NROWS);
    float avge = (float)ce * (1.0f / (float)NROWS);
    float Ha = block_sum_1024(avga * logf(avga + 1e-10f), red, tid);
    float He = block_sum_1024(avge * logf(avge + 1e-10f), red, tid);
    float perp_a = expf(-Ha);
    float perp_e = expf(-He);

    const float* sc = &g_scode[0][0];
    float mn = FLT_MAX;
    for (int i = tid; i < Bv * Bv; i += 1024) mn = fminf(mn, sc[i]);
    float maxS = -block_min_1024(mn, red, tid);

    float part = 0.f;
    if (tid < Bv) {
        float rs = 0.f, dg = 0.f;
        for (int j = 0; j < Bv; ++j) {
            float v = expf(sc[tid * Bv + j] + maxS);
            rs += v;
            if (j == tid) dg = v;
        }
        part = logf(dg / (rs + 1e-5f));
    }
    float Lsum = block_sum_1024(part, red, tid);
    float cmcm = 0.5f * (-Lsum / (float)Bv);

    float eq = (tid < Bv && g_mode[0][tid] == g_mode[1][tid]) ? 1.f : 0.f;
    float eqsum = block_sum_1024(eq, red, tid);

    if (tid == 0) {
        const float invBTD = 1.0f / (float)BTD;
        float a_loss = 0.25f * (2.f * sums4[0] + sums4[1]) * invBTD;
        float e_loss = 0.25f * (2.f * sums4[2] + sums4[3]) * invBTD;
        size_t base = 2 * BTD;
        out[base + 0] = a_loss;
        out[base + 1] = e_loss;
        out[base + 2] = perp_a;
        out[base + 3] = perp_e;
        out[base + 4] = cmcm;
        out[base + 5] = eqsum;
    }
}

// ---------------- launch ----------------
extern "C" void kernel_launch(void* const* d_in, const int* in_sizes, int n_in,
                              void* d_out, int out_size) {
    const float* audio = (const float*)d_in[0];
    const float* eeg   = (const float*)d_in[1];
    const float* emb   = (const float*)d_in[2];
    float* out = (float*)d_out;

    float *nA, *nE, *nB;
    cudaGetSymbolAddress((void**)&nA, g_norm_a);
    cudaGetSymbolAddress((void**)&nE, g_norm_e);
    cudaGetSymbolAddress((void**)&nB, g_norm_emb);
    __nv_bfloat16 *hA0, *hA1, *hB;
    cudaGetSymbolAddress((void**)&hA0, g_hiA);
    hA1 = hA0 + BTD;
    cudaGetSymbolAddress((void**)&hB, g_hiB);
    cudaFuncSetAttribute(gemm_tc_kernel, cudaFuncAttributeMaxDynamicSharedMemorySize, GEMM_SMEM);

    conv_norm_kernel<<<NROWS / 8, 256>>>(audio, hA0, nA);                     // 0
    conv_norm_kernel<<<NROWS / 8, 256>>>(eeg, hA1, nE);                       // 1
    conv_norm_kernel<<<Mv / 8, 256>>>(emb, hB, nB);                           // 2
    gemm_tc_kernel<<<dim3(NTILE, NROWS / 128, 2), 256, GEMM_SMEM>>>();        // 3 (profiled slot)
    merge_kernel<<<dim3(NROWS / 256, 2), 256>>>();                            // 4
    phase2_kernel<<<dim3(Bv, NCHUNK, 2), 256>>>();                            // 5
    ph_finalize_kernel<<<dim3(Bv, 2), 256>>>();                               // 6
    refine_kernel<<<dim3(NROWS / 8, 2), 256>>>(audio, eeg, emb);              // 7
    counts_kernel<<<dim3(Bv, 2), 256>>>();                                    // 8
    scode_kernel<<<Bv, 256>>>();                                              // 9
    output_loss_kernel<<<NROWS, 64>>>(audio, eeg, emb, out);                  // 10
    final_kernel<<<1, 1024>>>(out);                                           // 11
}

// round 17
// speedup vs baseline: 1.0920x; 1.0920x over previous
#include <cuda_runtime.h>
#include <cuda_bf16.h>
#include <cuda_fp16.h>
#include <math.h>
#include <float.h>
#include <stdint.h>

// Problem constants
#define Bv 64
#define Tv 512
#define Dv 256
#define Mv 1024
#define NROWS (Bv*Tv)          // 32768
#define BTD ((size_t)NROWS*Dv) // 8388608
#define NCHUNK 4               // phase2 T-split
#define NTILE 8
// self-consistent e-ratio window: (2e-3 bf16-GEMM + ~5e-4 fp16-delta) / (2*sqrt(256)) = 7.8e-5
#define TAU 1.2e-4f
#define CAND_CAP 63

// ---------------- static device scratch ----------------
__device__ __align__(16) __half g_d16[2][(size_t)NROWS*Mv];   // 128 MB: delta = ne - 2*dot
__device__ float g_norm_a[NROWS];
__device__ float g_norm_e[NROWS];
__device__ float g_norm_emb[Mv];
__device__ int   g_idx_a[NROWS];
__device__ int   g_idx_e[NROWS];
__device__ int   g_cand[2][NROWS][64];     // [0]=cnt, [1..63]=candidate idx
__device__ float g_php[2][Bv][NCHUNK][Mv];
__device__ float g_ph[2][Bv][Mv];
__device__ float g_lph[2][Bv][Mv];
__device__ int   g_cnt[2][Bv][Mv];
__device__ int   g_mode[2][Bv];
__device__ float g_scode[Bv][Bv];
__device__ float g_lpart[NROWS*4];
__device__ __align__(16) __nv_bfloat16 g_hiA[2][BTD];
__device__ __align__(16) __nv_bfloat16 g_hiB[Mv*Dv];

// ==================== PTX helpers (sm_80-compatible only) ====================
__device__ __forceinline__ uint32_t smem_u32(const void* p) {
    uint32_t a;
    asm("{ .reg .u64 t; cvta.to.shared.u64 t, %1; cvt.u32.u64 %0, t; }" : "=r"(a) : "l"(p));
    return a;
}
__device__ __forceinline__ void cp16(uint32_t s, const void* g) {
    asm volatile("cp.async.cg.shared.global [%0], [%1], 16;" :: "r"(s), "l"(g));
}
__device__ __forceinline__ void cp_commit() { asm volatile("cp.async.commit_group;" ::: "memory"); }
template<int N>
__device__ __forceinline__ void cp_wait() { asm volatile("cp.async.wait_group %0;" :: "n"(N) : "memory"); }

__device__ __forceinline__ void ldsm4(uint32_t* r, uint32_t addr) {
    asm volatile("ldmatrix.sync.aligned.m8n8.x4.shared.b16 {%0,%1,%2,%3}, [%4];"
        : "=r"(r[0]), "=r"(r[1]), "=r"(r[2]), "=r"(r[3]) : "r"(addr));
}
__device__ __forceinline__ void mma_bf16(float* c, const uint32_t* a, const uint32_t* b) {
    asm volatile("mma.sync.aligned.m16n8k16.row.col.f32.bf16.bf16.f32 "
        "{%0,%1,%2,%3}, {%4,%5,%6,%7}, {%8,%9}, {%0,%1,%2,%3};"
        : "+f"(c[0]), "+f"(c[1]), "+f"(c[2]), "+f"(c[3])
        : "r"(a[0]), "r"(a[1]), "r"(a[2]), "r"(a[3]), "r"(b[0]), "r"(b[1]));
}
__device__ __forceinline__ uint32_t sw128(uint32_t o) { return o ^ ((o >> 3) & 0x70); }

// ---------------- fused convert(fp32->bf16) + row norms (warp-per-row, MLP=2) ----------------
__global__ __launch_bounds__(256)
void conv_norm_kernel(const float* __restrict__ src,
                      __nv_bfloat16* __restrict__ dstB,
                      float* __restrict__ dstN) {
    const int wid = threadIdx.x >> 5, lane = threadIdx.x & 31;
    const int row = blockIdx.x * 8 + wid;
    const float4* s4 = (const float4*)(src + (size_t)row * Dv);
    float4 v0 = s4[lane];
    float4 v1 = s4[lane + 32];
    union { __nv_bfloat16 b[4]; uint2 u; } H0, H1;
    H0.b[0] = __float2bfloat16(v0.x); H0.b[1] = __float2bfloat16(v0.y);
    H0.b[2] = __float2bfloat16(v0.z); H0.b[3] = __float2bfloat16(v0.w);
    H1.b[0] = __float2bfloat16(v1.x); H1.b[1] = __float2bfloat16(v1.y);
    H1.b[2] = __float2bfloat16(v1.z); H1.b[3] = __float2bfloat16(v1.w);
    uint2* d4 = (uint2*)(dstB + (size_t)row * Dv);
    d4[lane] = H0.u;
    d4[lane + 32] = H1.u;
    float ss = v0.x*v0.x + v0.y*v0.y + v0.z*v0.z + v0.w*v0.w
             + v1.x*v1.x + v1.y*v1.y + v1.z*v1.z + v1.w*v1.w;
    #pragma unroll
    for (int off = 16; off; off >>= 1) ss += __shfl_xor_sync(0xffffffffu, ss, off);
    if (lane == 0) dstN[row] = ss;
}

// ---------------- HMMA bf16 GEMM -> fp16 delta = ne - 2*dot (lean epilogue) ----------------
#define TILE_B   16384
#define STAGE_B  (2*TILE_B)
#define NBUF     3
#define GEMM_SMEM (NBUF*STAGE_B)       // 96 KB

__device__ __forceinline__ void load_stage(uint32_t stBase, int rowBase, int colBase, int s,
                                           const __nv_bfloat16* __restrict__ Ahi,
                                           int tid) {
    #pragma unroll
    for (int j = 0; j < 8; ++j) {
        int id = j * 256 + tid;
        int t = id >> 10;
        int local = id & 1023;
        int row = local >> 3;
        int c = local & 7;
        const __nv_bfloat16* src = t ? g_hiB : Ahi;
        int grow = (t ? colBase : rowBase) + row;
        uint32_t so = stBase + t * TILE_B + sw128((uint32_t)(row * 128 + c * 16));
        cp16(so, src + (size_t)grow * Dv + s * 64 + c * 8);
    }
}

__global__ __launch_bounds__(256, 2)
void gemm_tc_kernel() {
    extern __shared__ char sm[];
    const uint32_t smem = smem_u32(sm);
    const int tid  = threadIdx.x;
    const int wid  = tid >> 5;
    const int lane = tid & 31;
    const int mod  = blockIdx.z;
    const int rowBase = blockIdx.y * 128;
    const int colBase = blockIdx.x * 128;
    const __nv_bfloat16* Ahi = g_hiA[mod];

    const int mb = (wid >> 2) * 64;
    const int nb = (wid & 3) * 32;

    const uint32_t aRow = (uint32_t)(mb + (lane & 15));
    const uint32_t aK16 = (uint32_t)((lane >> 4) * 16);
    const uint32_t bRow = (uint32_t)(nb + ((lane >> 4) << 3) + (lane & 7));
    const uint32_t bK16 = (uint32_t)(((lane >> 3) & 1) * 16);

    float acc[4][4][4];
    #pragma unroll
    for (int i = 0; i < 4; ++i)
        #pragma unroll
        for (int j = 0; j < 4; ++j)
            #pragma unroll
            for (int k = 0; k < 4; ++k) acc[i][j][k] = 0.f;

    load_stage(smem + 0 * STAGE_B, rowBase, colBase, 0, Ahi, tid); cp_commit();
    load_stage(smem + 1 * STAGE_B, rowBase, colBase, 1, Ahi, tid); cp_commit();
    load_stage(smem + 2 * STAGE_B, rowBase, colBase, 2, Ahi, tid); cp_commit();

    #pragma unroll
    for (int s = 0; s < 4; ++s) {
        if (s == 0) cp_wait<2>();
        else if (s == 1) cp_wait<2>();
        else if (s == 2) cp_wait<1>();
        else cp_wait<0>();
        __syncthreads();
        const uint32_t stBase = smem + (s % NBUF) * STAGE_B;
        const uint32_t aHiB = stBase;
        const uint32_t bHiB = stBase + TILE_B;

        #pragma unroll
        for (int kk = 0; kk < 4; ++kk) {
            const uint32_t kb = (uint32_t)(kk * 32);
            uint32_t ahi[4][4], bhi[2][4];
            #pragma unroll
            for (int mt = 0; mt < 4; ++mt) {
                uint32_t off = sw128((aRow + mt * 16) * 128 + kb + aK16);
                ldsm4(ahi[mt], aHiB + off);
            }
            #pragma unroll
            for (int p = 0; p < 2; ++p) {
                uint32_t off = sw128((bRow + p * 16) * 128 + kb + bK16);
                ldsm4(bhi[p], bHiB + off);
            }
            #pragma unroll
            for (int mt = 0; mt < 4; ++mt)
                #pragma unroll
                for (int nt = 0; nt < 4; ++nt)
                    mma_bf16(acc[mt][nt], ahi[mt], &bhi[nt >> 1][(nt & 1) * 2]);
        }
        if (s == 0) {
            __syncthreads();
            load_stage(smem + 0 * STAGE_B, rowBase, colBase, 3, Ahi, tid);
            cp_commit();
        }
    }

    // lean epilogue: delta = ne - 2*dot, fp16 store (no rn, no MUFU, no reductions)
    __half* dst = g_d16[mod];
    const int q = lane >> 2;
    const int cpair = (lane & 3) * 2;
    #pragma unroll
    for (int mt = 0; mt < 4; ++mt) {
        const int r0 = rowBase + mb + mt * 16 + q;
        const int r1 = r0 + 8;
        #pragma unroll
        for (int nt = 0; nt < 4; ++nt) {
            const int col = colBase + nb + nt * 8 + cpair;
            const float2 ne = *(const float2*)&g_norm_emb[col];
            float a0 = ne.x - 2.0f * acc[mt][nt][0];
            float a1 = ne.y - 2.0f * acc[mt][nt][1];
            float b0 = ne.x - 2.0f * acc[mt][nt][2];
            float b1 = ne.y - 2.0f * acc[mt][nt][3];
            *(__half2*)(dst + (size_t)r0 * Mv + col) = __floats2half2_rn(a0, a1);
            *(__half2*)(dst + (size_t)r1 * Mv + col) = __floats2half2_rn(b0, b1);
        }
    }
}

// ---------------- phase2: softmax(-sqrt(rn+delta)) + self-consistent candidates ----------------
__global__ __launch_bounds__(256, 4)
void phase2_kernel() {
    const int b     = blockIdx.x;
    const int chunk = blockIdx.y;
    const int mod   = blockIdx.z;

    __shared__ float ph[8][Mv];   // per-warp private accumulators (32 KB)
    __shared__ int scand[8][CAND_CAP];
    __shared__ int scnt[8];

    const int tid = threadIdx.x;
    const int w = tid >> 5, lane = tid & 31;
    const float* rnArr = mod ? g_norm_e : g_norm_a;

    for (int m = lane; m < Mv; m += 32) ph[w][m] = 0.f;
    __syncthreads();

    const int t0 = chunk * (Tv / NCHUNK);
    const int t1 = t0 + (Tv / NCHUNK);
    for (int t = t0 + w; t < t1; t += 8) {
        const int row = b * Tv + t;
        const uint2* drow = (const uint2*)(g_d16[mod] + (size_t)row * Mv);
        const float rn = rnArr[row];
        float e[32];
        float sum = 0.f, emax = 0.f;
        #pragma unroll
        for (int jj = 0; jj < 8; ++jj) {
            uint2 dv = drow[jj * 32 + lane];
            float2 f0 = __half22float2(*(__half2*)&dv.x);
            float2 f1 = __half22float2(*(__half2*)&dv.y);
            float dd[4] = {rn + f0.x, rn + f0.y, rn + f1.x, rn + f1.y};
            #pragma unroll
            for (int c = 0; c < 4; ++c) {
                float ev = __expf(-sqrtf(fmaxf(dd[c], 0.f)));
                e[jj * 4 + c] = ev;
                sum += ev;
                emax = fmaxf(emax, ev);
            }
        }
        #pragma unroll
        for (int off = 16; off; off >>= 1) {
            sum += __shfl_xor_sync(0xffffffffu, sum, off);
            emax = fmaxf(emax, __shfl_xor_sync(0xffffffffu, emax, off));
        }
        const float inv = 1.f / sum;
        const float thr = emax * (1.0f - TAU);
        if (lane == 0) scnt[w] = 0;
        __syncwarp();

        uint32_t lmask = 0;
        #pragma unroll
        for (int jj = 0; jj < 8; ++jj) {
            float4* p = (float4*)&ph[w][jj * 128 + lane * 4];
            float4 v = *p;
            float e0 = e[jj*4+0], e1 = e[jj*4+1], e2 = e[jj*4+2], e3 = e[jj*4+3];
            v.x += e0 * inv; v.y += e1 * inv; v.z += e2 * inv; v.w += e3 * inv;
            *p = v;
            if (e0 >= thr) lmask |= 1u << (jj*4+0);
            if (e1 >= thr) lmask |= 1u << (jj*4+1);
            if (e2 >= thr) lmask |= 1u << (jj*4+2);
            if (e3 >= thr) lmask |= 1u << (jj*4+3);
        }
        while (lmask) {
            int bp = __ffs(lmask) - 1;
            lmask &= lmask - 1;
            int idx = (bp >> 2) * 128 + lane * 4 + (bp & 3);
            int pos = atomicAdd(&scnt[w], 1);
            if (pos < CAND_CAP) scand[w][pos] = idx;
        }
        __syncwarp();
        if (lane == 0) {
            int c = scnt[w]; if (c > CAND_CAP) c = CAND_CAP;
            int* dst = g_cand[mod][row];
            dst[0] = c;
            for (int k = 0; k < c; ++k) dst[k + 1] = scand[w][k];
        }
        __syncwarp();
    }
    __syncthreads();

    for (int m = tid; m < Mv; m += 256) {
        float v = 0.f;
        #pragma unroll
        for (int ww = 0; ww < 8; ++ww) v += ph[ww][m];
        g_php[mod][b][chunk][m] = v;
    }
}

// ---------------- ph finalize: chunk reduce + mean + log ----------------
__global__ void ph_finalize_kernel() {
    const int b = blockIdx.x, mod = blockIdx.y;
    const float invT = 1.f / (float)Tv;
    for (int m = threadIdx.x; m < Mv; m += 256) {
        float v = (g_php[mod][b][0][m] + g_php[mod][b][1][m])
                + (g_php[mod][b][2][m] + g_php[mod][b][3][m]);
        v *= invT;
        g_ph[mod][b][m]  = v;
        g_lph[mod][b][m] = logf(v + 1e-10f);
    }
}

// ---------------- refine: reference-rounding argmin over window candidates ----------------
__device__ __forceinline__ void dot2_acc(float a, float b, float& s, float& c) {
    float p  = a * b;
    float e1 = fmaf(a, b, -p);
    float t  = s + p;
    float z  = t - s;
    float e2 = (s - (t - z)) + (p - z);
    s = t;
    c += e1 + e2;
}

__global__ __launch_bounds__(256)
void refine_kernel(const float* __restrict__ audio,
                   const float* __restrict__ eeg,
                   const float* __restrict__ emb) {
    const int w = threadIdx.x >> 5, lane = threadIdx.x & 31;
    const int row = blockIdx.x * 8 + w;
    const int mod = blockIdx.y;
    const int* cd = g_cand[mod][row];
    int cnt = __ldg(&cd[0]);
    if (cnt <= 1) {
        if (lane == 0) (mod ? g_idx_e : g_idx_a)[row] = __ldg(&cd[1]);
        return;
    }
    if (cnt > CAND_CAP) cnt = CAND_CAP;

    const float* x = (mod ? eeg : audio) + (size_t)row * Dv;
    float xr[8];
    *(float4*)&xr[0] = *(const float4*)(x + lane * 8);
    *(float4*)&xr[4] = *(const float4*)(x + lane * 8 + 4);
    const float rn = (mod ? g_norm_e : g_norm_a)[row];

    float bestF = FLT_MAX; int bestI = 0x7fffffff;
    for (int k = 0; k < cnt; ++k) {
        int ci = __ldg(&cd[k + 1]);
        const float* e = emb + (size_t)ci * Dv + lane * 8;
        float4 a = *(const float4*)e;
        float4 bb = *(const float4*)(e + 4);
        float s = 0.f, comp = 0.f;
        dot2_acc(xr[0], a.x, s, comp);  dot2_acc(xr[1], a.y, s, comp);
        dot2_acc(xr[2], a.z, s, comp);  dot2_acc(xr[3], a.w, s, comp);
        dot2_acc(xr[4], bb.x, s, comp); dot2_acc(xr[5], bb.y, s, comp);
        dot2_acc(xr[6], bb.z, s, comp); dot2_acc(xr[7], bb.w, s, comp);
        float d = s + comp;
        #pragma unroll
        for (int off = 16; off; off >>= 1) d += __shfl_xor_sync(0xffffffffu, d, off);
        float tt = rn + g_norm_emb[ci];   // fp32 rounding (reference grid)
        float f  = tt - 2.0f * d;         // fp32 rounding
        if (f < bestF || (f == bestF && ci < bestI)) { bestF = f; bestI = ci; }
    }
    if (lane == 0) (mod ? g_idx_e : g_idx_a)[row] = bestI;
}

// ---------------- counts + mode per (b, mod) ----------------
__global__ __launch_bounds__(256)
void counts_kernel() {
    const int b = blockIdx.x;
    const int mod = blockIdx.y;
    const int tid = threadIdx.x;
    const int* idxArr = mod ? g_idx_e : g_idx_a;
    __shared__ int cnt[Mv];
    __shared__ int rbc[256], rbi[256];
    for (int m = tid; m < Mv; m += 256) cnt[m] = 0;
    __syncthreads();
    for (int t = tid; t < Tv; t += 256) atomicAdd(&cnt[idxArr[b * Tv + t]], 1);
    __syncthreads();
    for (int m = tid; m < Mv; m += 256) g_cnt[mod][b][m] = cnt[m];
    int bi = Mv, bc = -1;
    for (int m = tid; m < Mv; m += 256) {
        int cc = cnt[m];
        if (cc > bc) { bc = cc; bi = m; }
    }
    rbc[tid] = bc; rbi[tid] = bi;
    __syncthreads();
    for (int st = 128; st; st >>= 1) {
        if (tid < st) {
            if (rbc[tid + st] > rbc[tid] ||
                (rbc[tid + st] == rbc[tid] && rbi[tid + st] < rbi[tid])) {
                rbc[tid] = rbc[tid + st]; rbi[tid] = rbi[tid + st];
            }
        }
        __syncthreads();
    }
    if (tid == 0) g_mode[mod][b] = rbi[0];
}

// ---------------- Scode [64,64] ----------------
__global__ void scode_kernel() {
    __shared__ float ap[Mv], ep[Mv], partial[256];
    const int i = blockIdx.x, tid = threadIdx.x;
    for (int m = tid; m < Mv; m += 256) { ap[m] = g_ph[0][i][m]; ep[m] = g_ph[1][i][m]; }
    __syncthreads();
    const int j = tid & 63, part = tid >> 6;
    float sum = 0.f;
    const int k0 = part * 256;
    for (int k = k0; k < k0 + 256; ++k)
        sum += ap[k] * g_lph[1][j][k] + ep[k] * g_lph[0][j][k];
    partial[tid] = sum;
    __syncthreads();
    if (tid < 64)
        g_scode[i][tid] = partial[tid] + partial[tid + 64] + partial[tid + 128] + partial[tid + 192];
}

// ---------------- gather quantized outputs + MSE partials (vectorized) ----------------
__global__ __launch_bounds__(64)
void output_loss_kernel(const float* __restrict__ audio,
                        const float* __restrict__ eeg,
                        const float* __restrict__ emb,
                        float* __restrict__ out) {
    const int n = blockIdx.x;
    const int tid = threadIdx.x;
    const int ia = g_idx_a[n], ie = g_idx_e[n];
    const size_t off4 = (size_t)n * (Dv / 4) + tid;
    float4 av = ((const float4*)audio)[off4];
    float4 ev = ((const float4*)eeg)[off4];
    float4 qa = ((const float4*)(emb + (size_t)ia * Dv))[tid];
    float4 qe = ((const float4*)(emb + (size_t)ie * Dv))[tid];
    ((float4*)out)[off4]             = qa;
    ((float4*)out)[BTD / 4 + off4]   = qe;
    float daa = (av.x-qa.x)*(av.x-qa.x) + (av.y-qa.y)*(av.y-qa.y)
              + (av.z-qa.z)*(av.z-qa.z) + (av.w-qa.w)*(av.w-qa.w);
    float dae = (av.x-qe.x)*(av.x-qe.x) + (av.y-qe.y)*(av.y-qe.y)
              + (av.z-qe.z)*(av.z-qe.z) + (av.w-qe.w)*(av.w-qe.w);
    float dee = (ev.x-qe.x)*(ev.x-qe.x) + (ev.y-qe.y)*(ev.y-qe.y)
              + (ev.z-qe.z)*(ev.z-qe.z) + (ev.w-qe.w)*(ev.w-qe.w);
    float dea = (ev.x-qa.x)*(ev.x-qa.x) + (ev.y-qa.y)*(ev.y-qa.y)
              + (ev.z-qa.z)*(ev.z-qa.z) + (ev.w-qa.w)*(ev.w-qa.w);
    #pragma unroll
    for (int o = 16; o; o >>= 1) {
        daa += __shfl_xor_sync(0xffffffffu, daa, o);
        dae += __shfl_xor_sync(0xffffffffu, dae, o);
        dee += __shfl_xor_sync(0xffffffffu, dee, o);
        dea += __shfl_xor_sync(0xffffffffu, dea, o);
    }
    __shared__ float sred[4][2];
    const int w = tid >> 5, lane = tid & 31;
    if (lane == 0) { sred[0][w] = daa; sred[1][w] = dae; sred[2][w] = dee; sred[3][w] = dea; }
    __syncthreads();
    if (tid < 4) g_lpart[(size_t)n * 4 + tid] = sred[tid][0] + sred[tid][1];
}

// ---------------- scalars (also reduces MSE partials) ----------------
__device__ __forceinline__ float block_sum_1024(float v, float* red, int tid) {
    red[tid] = v; __syncthreads();
    for (int s = 512; s; s >>= 1) { if (tid < s) red[tid] += red[tid + s]; __syncthreads(); }
    float r = red[0]; __syncthreads(); return r;
}
__device__ __forceinline__ float block_min_1024(float v, float* red, int tid) {
    red[tid] = v; __syncthreads();
    for (int s = 512; s; s >>= 1) { if (tid < s) red[tid] = fminf(red[tid], red[tid + s]); __syncthreads(); }
    float r = red[0]; __syncthreads(); return r;
}

__global__ void final_kernel(float* __restrict__ out) {
    __shared__ float red[1024];
    __shared__ float sums4[4];
    const int tid = threadIdx.x;

    {
        const int c = tid & 3;
        float v = 0.f;
        for (int i = (tid >> 2); i < NROWS; i += 256) v += g_lpart[(size_t)i * 4 + c];
        red[tid] = v; __syncthreads();
        for (int s = 512; s >= 4; s >>= 1) {
            if (tid < s) red[tid] += red[tid + s];
            __syncthreads();
        }
        if (tid < 4) sums4[tid] = red[tid];
        __syncthreads();
    }

    int ca = 0, ce = 0;
    for (int b = 0; b < Bv; ++b) { ca += g_cnt[0][b][tid]; ce += g_cnt[1][b][tid]; }
    float avga = (float)ca * (1.0f / (float)NROWS);
    float avge = (float)ce * (1.0f / (float)NROWS);
    float Ha = block_sum_1024(avga * logf(avga + 1e-10f), red, tid);
    float He = block_sum_1024(avge * logf(avge + 1e-10f), red, tid);
    float perp_a = expf(-Ha);
    float perp_e = expf(-He);

    const float* sc = &g_scode[0][0];
    float mn = FLT_MAX;
    for (int i = tid; i < Bv * Bv; i += 1024) mn = fminf(mn, sc[i]);
    float maxS = -block_min_1024(mn, red, tid);

    float part = 0.f;
    if (tid < Bv) {
        float rs = 0.f, dg = 0.f;
        for (int j = 0; j < Bv; ++j) {
            float v = expf(sc[tid * Bv + j] + maxS);
            rs += v;
            if (j == tid) dg = v;
        }
        part = logf(dg / (rs + 1e-5f));
    }
    float Lsum = block_sum_1024(part, red, tid);
    float cmcm = 0.5f * (-Lsum / (float)Bv);

    float eq = (tid < Bv && g_mode[0][tid] == g_mode[1][tid]) ? 1.f : 0.f;
    float eqsum = block_sum_1024(eq, red, tid);

    if (tid == 0) {
        const float invBTD = 1.0f / (float)BTD;
        float a_loss = 0.25f * (2.f * sums4[0] + sums4[1]) * invBTD;
        float e_loss = 0.25f * (2.f * sums4[2] + sums4[3]) * invBTD;
        size_t base = 2 * BTD;
        out[base + 0] = a_loss;
        out[base + 1] = e_loss;
        out[base + 2] = perp_a;
        out[base + 3] = perp_e;
        out[base + 4] = cmcm;
        out[base + 5] = eqsum;
    }
}

// ---------------- launch ----------------
extern "C" void kernel_launch(void* const* d_in, const int* in_sizes, int n_in,
                              void* d_out, int out_size) {
    const float* audio = (const float*)d_in[0];
    const float* eeg   = (const float*)d_in[1];
    const float* emb   = (const float*)d_in[2];
    float* out = (float*)d_out;

    float *nA, *nE, *nB;
    cudaGetSymbolAddress((void**)&nA, g_norm_a);
    cudaGetSymbolAddress((void**)&nE, g_norm_e);
    cudaGetSymbolAddress((void**)&nB, g_norm_emb);
    __nv_bfloat16 *hA0, *hA1, *hB;
    cudaGetSymbolAddress((void**)&hA0, g_hiA);
    hA1 = hA0 + BTD;
    cudaGetSymbolAddress((void**)&hB, g_hiB);
    cudaFuncSetAttribute(gemm_tc_kernel, cudaFuncAttributeMaxDynamicSharedMemorySize, GEMM_SMEM);

    conv_norm_kernel<<<NROWS / 8, 256>>>(audio, hA0, nA);                     // 0
    conv_norm_kernel<<<NROWS / 8, 256>>>(eeg, hA1, nE);                       // 1
    conv_norm_kernel<<<Mv / 8, 256>>>(emb, hB, nB);                           // 2
    gemm_tc_kernel<<<dim3(Mv / 128, NROWS / 128, 2), 256, GEMM_SMEM>>>();     // 3 (profiled slot)
    phase2_kernel<<<dim3(Bv, NCHUNK, 2), 256>>>();                            // 4
    ph_finalize_kernel<<<dim3(Bv, 2), 256>>>();                               // 5
    refine_kernel<<<dim3(NROWS / 8, 2), 256>>>(audio, eeg, emb);              // 6
    counts_kernel<<<dim3(Bv, 2), 256>>>();                                    // 7
    scode_kernel<<<Bv, 256>>>();                                              // 8
    output_loss_kernel<<<NROWS, 64>>>(audio, eeg, emb, out);                  // 9
    final_kernel<<<1, 1024>>>(out);                                           // 10
}